// round 4
// baseline (speedup 1.0000x reference)
#include <cuda_runtime.h>
#include <cuda_bf16.h>

// Problem shape (fixed)
#define BB_ 64
#define SS_ 512
#define HH_ 1024
#define LL_ 9

#define TPB 256
#define WARPS 8
#define ROWS_PER_WARP 4
#define ROWS_PER_BLOCK 32         // 8 warps * 4 rows
#define NCHUNK 16                 // 512 / 32

// Transposed weights [L][H], written once by transpose_W
__device__ float g_Wt[LL_ * HH_];

typedef unsigned long long u64;

__device__ __forceinline__ u64 fma2(u64 a, u64 b, u64 c) {
    u64 d;
    asm("fma.rn.f32x2 %0, %1, %2, %3;" : "=l"(d) : "l"(a), "l"(b), "l"(c));
    return d;
}
__device__ __forceinline__ u64 add2(u64 a, u64 b) {
    u64 d;
    asm("add.rn.f32x2 %0, %1, %2;" : "=l"(d) : "l"(a), "l"(b));
    return d;
}
__device__ __forceinline__ float pair_sum(u64 v) {
    float lo = __uint_as_float((unsigned)(v & 0xffffffffull));
    float hi = __uint_as_float((unsigned)(v >> 32));
    return lo + hi;
}

// ---------------------------------------------------------------------------
// One-shot: W [H,L] -> g_Wt [L,H]
// ---------------------------------------------------------------------------
__global__ void transpose_W(const float* __restrict__ W) {
    int j = blockIdx.x;
    int k = threadIdx.x;
    g_Wt[j * HH_ + k] = W[k * LL_ + j];
}

// ---------------------------------------------------------------------------
// Main kernel: block = 32 rows of one batch. Inline mask scan -> src indices.
// Warp computes 4 rows; half-warps split the 9 outputs (j0..3 / j4..8).
// k-loop processes 2 iterations per step with all 8 LDG.128 front-batched.
// ---------------------------------------------------------------------------
__global__ __launch_bounds__(TPB, 2)
void bertner_main_kernel(const float* __restrict__ seq,
                         const int* __restrict__ mask,
                         const float* __restrict__ bias,
                         float* __restrict__ out) {
    __shared__ ulonglong2 sW2[LL_ * 256];    // [j][k4] 36 KB
    __shared__ unsigned mbits[NCHUNK];
    __shared__ int msum[NCHUNK];
    __shared__ int ssrc[ROWS_PER_BLOCK];
    __shared__ int snv;
    __shared__ float sb[LL_];

    int tid  = threadIdx.x;
    int lane = tid & 31;
    int warp = tid >> 5;                      // 0..7

    int b  = blockIdx.x >> 4;                 // 16 blocks per batch
    int d0 = (blockIdx.x & 15) * ROWS_PER_BLOCK;

    if (tid < LL_) sb[tid] = bias[tid];

    // ---- per-block mask scan (512 bits) ----
    #pragma unroll
    for (int r = 0; r < 2; r++) {
        int chunk = warp * 2 + r;             // 0..15
        int s = chunk * 32 + lane;
        int m = (mask[b * SS_ + s] != 0);
        unsigned bal = __ballot_sync(0xffffffffu, m);
        if (lane == 0) mbits[chunk] = bal;
    }
    __syncthreads();
    if (tid < NCHUNK) {
        int v = __popc(mbits[tid]);
        #pragma unroll
        for (int off = 1; off < NCHUNK; off <<= 1) {
            int u = __shfl_up_sync(0x0000ffffu, v, off);
            if (tid >= off) v += u;
        }
        msum[tid] = v;                         // inclusive
        if (tid == NCHUNK - 1) snv = v;
    }
    __syncthreads();
    int nv = snv;
    bool blockHasValid = (d0 < nv);

    // ---- source index for each of this block's 32 rows ----
    if (tid < ROWS_PER_BLOCK) {
        int d = d0 + tid;
        int src = 0;
        if (d < nv) {
            int c = 0, base = 0;
            #pragma unroll
            for (int cc = 0; cc < NCHUNK - 1; cc++)
                if (msum[cc] <= d) { c = cc + 1; base = msum[cc]; }
            unsigned wv = mbits[c];
            int rr = d - base;
            for (int t = 0; t < rr; t++) wv &= wv - 1;
            src = c * 32 + (__ffs(wv) - 1);
        }
        ssrc[tid] = src;
    }

    // ---- stage transposed W (conflict-free float4 memcpy) ----
    if (blockHasValid) {
        const float4* s4 = (const float4*)g_Wt;
        float4* dd4 = (float4*)sW2;
        #pragma unroll
        for (int it = 0; it < (LL_ * HH_ / 4) / TPB; it++)   // 9
            dd4[it * TPB + tid] = s4[it * TPB + tid];
    }
    __syncthreads();

    // ---- main GEMV ----
    int jg = lane >> 4;                        // 0: j0..3, 1: j4..8
    int kl = lane & 15;
    int jbase = jg * 4;

    int rw0 = warp * ROWS_PER_WARP;
    bool warpValid = (d0 + rw0) < nv;

    bool vld[ROWS_PER_WARP];
    const ulonglong2* xp[ROWS_PER_WARP];
    #pragma unroll
    for (int p = 0; p < ROWS_PER_WARP; p++) {
        int d = d0 + rw0 + p;
        vld[p] = (d < nv);
        int src = ssrc[rw0 + p];
        xp[p] = (const ulonglong2*)(seq + ((size_t)b * SS_ + (size_t)src) * HH_);
    }

    u64 acc[ROWS_PER_WARP][5];
    #pragma unroll
    for (int p = 0; p < ROWS_PER_WARP; p++)
        #pragma unroll
        for (int jj = 0; jj < 5; jj++) acc[p][jj] = 0ull;

    if (warpValid) {
        #pragma unroll
        for (int i = 0; i < 16; i += 2) {
            int k4a = i * 16 + kl;
            int k4b = k4a + 16;
            // front-batch all 8 LDG.128 for two k-iterations
            ulonglong2 xa[ROWS_PER_WARP], xb[ROWS_PER_WARP];
            #pragma unroll
            for (int p = 0; p < ROWS_PER_WARP; p++) {
                xa[p] = make_ulonglong2(0ull, 0ull);
                xb[p] = make_ulonglong2(0ull, 0ull);
                if (vld[p]) {
                    xa[p] = xp[p][k4a];
                    xb[p] = xp[p][k4b];
                }
            }
            #pragma unroll
            for (int jj = 0; jj < 5; jj++) {
                if (jj < 4 || jg) {
                    ulonglong2 wA = sW2[(jbase + jj) * 256 + k4a];
                    #pragma unroll
                    for (int p = 0; p < ROWS_PER_WARP; p++) {
                        acc[p][jj] = fma2(xa[p].x, wA.x, acc[p][jj]);
                        acc[p][jj] = fma2(xa[p].y, wA.y, acc[p][jj]);
                    }
                }
            }
            #pragma unroll
            for (int jj = 0; jj < 5; jj++) {
                if (jj < 4 || jg) {
                    ulonglong2 wB = sW2[(jbase + jj) * 256 + k4b];
                    #pragma unroll
                    for (int p = 0; p < ROWS_PER_WARP; p++) {
                        acc[p][jj] = fma2(xb[p].x, wB.x, acc[p][jj]);
                        acc[p][jj] = fma2(xb[p].y, wB.y, acc[p][jj]);
                    }
                }
            }
        }
        // reduce over the 16 k-lanes of each half-warp
        #pragma unroll
        for (int p = 0; p < ROWS_PER_WARP; p++)
            #pragma unroll
            for (int jj = 0; jj < 5; jj++) {
                u64 a = acc[p][jj];
                #pragma unroll
                for (int off = 8; off >= 1; off >>= 1)
                    a = add2(a, __shfl_xor_sync(0xffffffffu, a, off));
                acc[p][jj] = a;
            }
    }

    // ---- epilogue: lane p (jg=0) assembles row p's 9 logits ----
    #pragma unroll
    for (int p = 0; p < ROWS_PER_WARP; p++) {
        float v[5];
        #pragma unroll
        for (int jj = 0; jj < 5; jj++) v[jj] = pair_sum(acc[p][jj]);
        float hi[5];
        #pragma unroll
        for (int jj = 0; jj < 5; jj++)
            hi[jj] = __shfl_xor_sync(0xffffffffu, v[jj], 16);
        if (lane == p) {
            float l[LL_];
            l[0] = v[0]; l[1] = v[1]; l[2] = v[2]; l[3] = v[3];
            l[4] = hi[0]; l[5] = hi[1]; l[6] = hi[2]; l[7] = hi[3]; l[8] = hi[4];
            float mx = -3.402823466e+38f;
            #pragma unroll
            for (int j = 0; j < LL_; j++) {
                l[j] += sb[j];
                mx = fmaxf(mx, l[j]);
            }
            float ssum = 0.0f;
            #pragma unroll
            for (int j = 0; j < LL_; j++) {
                l[j] = __expf(l[j] - mx);
                ssum += l[j];
            }
            float inv = __fdividef(1.0f, ssum);
            int rglob = b * SS_ + d0 + rw0 + p;
            float* o = out + (size_t)rglob * LL_;
            #pragma unroll
            for (int j = 0; j < LL_; j++) o[j] = l[j] * inv;
        }
    }
}

// ---------------------------------------------------------------------------
extern "C" void kernel_launch(void* const* d_in, const int* in_sizes, int n_in,
                              void* d_out, int out_size) {
    const float* seq  = (const float*)d_in[0];   // [B,S,H] f32
    const int*   mask = (const int*)d_in[1];     // [B,S]   i32
    const float* W    = (const float*)d_in[2];   // [H,L]   f32
    const float* bias = (const float*)d_in[3];   // [L]     f32
    float* out = (float*)d_out;                  // [B,S,L] f32

    transpose_W<<<LL_, HH_>>>(W);

    int grid = (BB_ * SS_) / ROWS_PER_BLOCK;     // 1024
    bertner_main_kernel<<<grid, TPB>>>(seq, mask, bias, out);
}